// round 13
// baseline (speedup 1.0000x reference)
#include <cuda_runtime.h>
#include <cuda.h>
#include <cuda_bf16.h>
#include <cstdint>

typedef unsigned long long ull;

// ---------------------------------------------------------------------------
// Scratch (bf16 hi/lo-split GEMM operands, K=48 per row = 96 B)
//   g_A[m][48]: [Phi(16) | Phi(16) | Plo(16)]
//   g_W[v][48]: [Whi(16) | Wlo(16) | Whi(16)]
// D = Phi*Whi + Phi*Wlo + Plo*Whi (+ bias in epilogue); lo*lo term ~2^-18
// ---------------------------------------------------------------------------
__device__ __align__(16) __nv_bfloat16 g_A[4096 * 48];
__device__ __align__(16) __nv_bfloat16 g_W[32000 * 48];

__device__ __forceinline__ uint32_t smem_u32(const void* p) {
    uint32_t a;
    asm("{ .reg .u64 t; cvta.to.shared.u64 t, %1; cvt.u32.u64 %0, t; }"
        : "=r"(a) : "l"(p));
    return a;
}
__device__ __forceinline__ void bf16_split(float x, __nv_bfloat16& hi, __nv_bfloat16& lo) {
    hi = __float2bfloat16(x);
    lo = __float2bfloat16(x - __bfloat162float(hi));
}

// ---------------------------------------------------------------------------
// Kernel 1 (fused): blocks [0, prepBlocks): half-warp-per-token circuit -> g_A
//                   blocks [prepBlocks, ...): W_out conversion        -> g_W
// ---------------------------------------------------------------------------
__global__ __launch_bounds__(256)
void prep_all_kernel(const int* __restrict__ ids,
                     const int* __restrict__ mask,
                     const float* __restrict__ We,
                     const float* __restrict__ gates,
                     const float* __restrict__ Wout,
                     int BS, int depth, int S, int B, int V, int prepBlocks) {
    if (blockIdx.x < (unsigned)prepBlocks) {
        __shared__ float sgt[2 * 256];   // transposed: sgt[l*256 + d*16 + o]
        for (int i = threadIdx.x; i < depth * 256; i += 256) {
            int l = i >> 8, r = i & 255, o = r >> 4, d = r & 15;
            sgt[l * 256 + d * 16 + o] = gates[i];
        }
        __syncthreads();

        int lane = threadIdx.x & 31, wid = threadIdx.x >> 5;
        int half = lane >> 4, k = lane & 15;
        int m = blockIdx.x * 16 + wid * 2 + half;
        if (m >= BS) return;

        int tok = ids[m];
        float e = We[(size_t)tok * 16 + k];
        float s = e * e;
#pragma unroll
        for (int off = 8; off; off >>= 1)
            s += __shfl_xor_sync(0xffffffffu, s, off, 16);
        e *= 1.f / (sqrtf(s) + 1e-12f);
        float st = e;

        for (int l = 0; l < depth; l++) {
            float acc = 0.f;
            const float* g = sgt + l * 256 + k;
#pragma unroll
            for (int d = 0; d < 16; d++) {
                float sd = __shfl_sync(0xffffffffu, st, d, 16);
                acc = fmaf(sd, g[d * 16], acc);
            }
            float x = acc * (0.99f * 0.99f) + (0.01f / 16.f);
            float s2 = x * x;
#pragma unroll
            for (int off = 8; off; off >>= 1)
                s2 += __shfl_xor_sync(0xffffffffu, s2, off, 16);
            st = x * (1.f / (sqrtf(s2) + 1e-12f));
        }
        st = st * 0.99f + (0.01f / 16.f);

        int s_pos = m % S;
        bool ap = true;
        for (int b = 0; b < B; b++) ap = ap && (mask[b * S + s_pos] != 0);

        float v = ap ? st : e;
        __nv_bfloat16 hi, lo; bf16_split(v, hi, lo);
        __nv_bfloat16* row = g_A + (size_t)m * 48;
        row[k] = hi; row[16 + k] = hi; row[32 + k] = lo;
    } else {
        int v = (blockIdx.x - prepBlocks) * 256 + threadIdx.x;
        if (v >= V) return;
        const float* wr = Wout + (size_t)v * 16;
        __nv_bfloat16* row = g_W + (size_t)v * 48;
#pragma unroll
        for (int k = 0; k < 16; k++) {
            __nv_bfloat16 hi, lo; bf16_split(wr[k], hi, lo);
            row[k] = hi; row[16 + k] = lo; row[32 + k] = hi;
        }
    }
}

// ---------------------------------------------------------------------------
// Kernel 2: HMMA bf16 GEMM, tile 128x128, 8 warps (2x4), K=48 — R11 mainloop
// verbatim. Epilogue NEW: fragments -> dense smem stage (union over dead A/B
// tiles) -> 2x cp.async.bulk.tensor.2d stores (TMA engine moves the whole
// tile smem->gmem: zero STG issue, zero L1TEX global-store wavefronts).
// Stage halves are dense 256B rows (TMA box {64,128}, f32, SWIZZLE_NONE).
// Fallback (use_tma==0): direct __stcs float2 stores (R11-equivalent).
// ---------------------------------------------------------------------------
#define SA 56   // tile smem row stride in bf16
#define SMEM_BYTES 65536

__global__ __launch_bounds__(256, 2)
void hmma_gemm_kernel(const __grid_constant__ CUtensorMap tmap,
                      const float* __restrict__ bout,
                      float* __restrict__ out, int V, int use_tma) {
    extern __shared__ __align__(16) char dsm[];
    __nv_bfloat16* sA = (__nv_bfloat16*)dsm;                 // 14336 B
    __nv_bfloat16* sB = (__nv_bfloat16*)(dsm + 14336);       // 14336 B
    float* s_bias = (float*)(dsm + 28672);                   //   512 B
    float* stage  = (float*)dsm;  // union after mainloop: 2 x 32768 B halves

    int tid = threadIdx.x, wid = tid >> 5, lane = tid & 31;
    int row0 = blockIdx.y * 128;
    int v0   = blockIdx.x * 128;

    // cooperative tile loads: 128 rows x 48 bf16 = 768 uint4 each (3/thread)
    {
        const uint4* srcA = (const uint4*)(g_A + (size_t)row0 * 48);
        const uint4* srcB = (const uint4*)(g_W + (size_t)v0 * 48);
#pragma unroll
        for (int i = tid; i < 768; i += 256) {
            int r = i / 6, c = i % 6;
            *(uint4*)(sA + r * SA + c * 8) = srcA[i];
            *(uint4*)(sB + r * SA + c * 8) = srcB[i];
        }
        if (tid < 32) ((float4*)s_bias)[tid] = ((const float4*)(bout + v0))[tid];
    }
    __syncthreads();

    int wm = wid >> 2;        // 0..1 : 64-row half
    int wn = wid & 3;         // 0..3 : 32-col quarter

    // ldmatrix lane->address mapping
    int aRowL = (lane & 7) + ((lane >> 3) & 1) * 8;
    int aColH = ((lane >> 4) & 1) * 8;
    int lb = lane & 15;
    int bRowL = lb & 7;
    int bColH = ((lb >> 3) & 1) * 8;

    uint32_t aBase = smem_u32(sA);
    uint32_t bBase = smem_u32(sB);

    float c[4][4][4];
#pragma unroll
    for (int mt = 0; mt < 4; mt++)
#pragma unroll
        for (int nt = 0; nt < 4; nt++)
#pragma unroll
            for (int j = 0; j < 4; j++) c[mt][nt][j] = 0.f;

#pragma unroll
    for (int k = 0; k < 3; k++) {
        uint32_t a[4][4], b[4][2];
#pragma unroll
        for (int mt = 0; mt < 4; mt++) {
            uint32_t addr = aBase +
                (uint32_t)(((wm * 64 + mt * 16 + aRowL) * SA + k * 16 + aColH) * 2);
            asm volatile("ldmatrix.sync.aligned.m8n8.x4.shared.b16 {%0,%1,%2,%3}, [%4];"
                         : "=r"(a[mt][0]), "=r"(a[mt][1]), "=r"(a[mt][2]), "=r"(a[mt][3])
                         : "r"(addr));
        }
#pragma unroll
        for (int nt = 0; nt < 4; nt++) {
            uint32_t addr = bBase +
                (uint32_t)(((wn * 32 + nt * 8 + bRowL) * SA + k * 16 + bColH) * 2);
            asm volatile("ldmatrix.sync.aligned.m8n8.x2.shared.b16 {%0,%1}, [%2];"
                         : "=r"(b[nt][0]), "=r"(b[nt][1]) : "r"(addr));
        }
#pragma unroll
        for (int mt = 0; mt < 4; mt++)
#pragma unroll
            for (int nt = 0; nt < 4; nt++)
                asm volatile(
                    "mma.sync.aligned.m16n8k16.row.col.f32.bf16.bf16.f32 "
                    "{%0,%1,%2,%3}, {%4,%5,%6,%7}, {%8,%9}, {%0,%1,%2,%3};"
                    : "+f"(c[mt][nt][0]), "+f"(c[mt][nt][1]),
                      "+f"(c[mt][nt][2]), "+f"(c[mt][nt][3])
                    : "r"(a[mt][0]), "r"(a[mt][1]), "r"(a[mt][2]), "r"(a[mt][3]),
                      "r"(b[nt][0]), "r"(b[nt][1]));
    }

    // bias add
    int rr = lane >> 2;
    int q2 = (lane & 3) * 2;
#pragma unroll
    for (int nt = 0; nt < 4; nt++) {
        float2 bv = *(const float2*)(s_bias + wn * 32 + nt * 8 + q2);
#pragma unroll
        for (int mt = 0; mt < 4; mt++) {
            c[mt][nt][0] += bv.x; c[mt][nt][1] += bv.y;
            c[mt][nt][2] += bv.x; c[mt][nt][3] += bv.y;
        }
    }

    if (use_tma) {
        __syncthreads();   // all ldmatrix/bias smem reads done; stage overwrites tiles
        // STS fragments into dense stage: half h = col>>6, 64 floats (256B) rows
#pragma unroll
        for (int mt = 0; mt < 4; mt++) {
            int r1 = wm * 64 + mt * 16 + rr;
#pragma unroll
            for (int nt = 0; nt < 4; nt++) {
                int col = wn * 32 + nt * 8 + q2;
                int h = col >> 6, cl = col & 63;
                *(float2*)(stage + h * 8192 + r1 * 64 + cl) =
                    make_float2(c[mt][nt][0], c[mt][nt][1]);
                *(float2*)(stage + h * 8192 + (r1 + 8) * 64 + cl) =
                    make_float2(c[mt][nt][2], c[mt][nt][3]);
            }
        }
        __syncthreads();
        if (tid == 0) {
            asm volatile("fence.proxy.async;" ::: "memory");
#pragma unroll
            for (int h = 0; h < 2; h++) {
                asm volatile(
                    "cp.async.bulk.tensor.2d.global.shared::cta.tile.bulk_group "
                    "[%0, {%1, %2}], [%3];"
                    :: "l"(&tmap), "r"(v0 + h * 64), "r"(row0),
                       "r"(smem_u32(stage + h * 8192))
                    : "memory");
            }
            asm volatile("cp.async.bulk.commit_group;" ::: "memory");
            asm volatile("cp.async.bulk.wait_group 0;" ::: "memory");
        }
    } else {
        // fallback: direct streaming float2 stores (R11-equivalent correctness)
#pragma unroll
        for (int mt = 0; mt < 4; mt++) {
            int grow = row0 + wm * 64 + mt * 16 + rr;
#pragma unroll
            for (int nt = 0; nt < 4; nt++) {
                int gcol = v0 + wn * 32 + nt * 8 + q2;
                __stcs((float2*)(out + (size_t)grow * V + gcol),
                       make_float2(c[mt][nt][0], c[mt][nt][1]));
                __stcs((float2*)(out + (size_t)(grow + 8) * V + gcol),
                       make_float2(c[mt][nt][2], c[mt][nt][3]));
            }
        }
    }
}

// ---------------------------------------------------------------------------
// Launch
// ---------------------------------------------------------------------------
typedef CUresult (*tmap_encode_fn)(
    CUtensorMap*, CUtensorMapDataType, cuuint32_t, void*,
    const cuuint64_t*, const cuuint64_t*, const cuuint32_t*, const cuuint32_t*,
    CUtensorMapInterleave, CUtensorMapSwizzle, CUtensorMapL2promotion,
    CUtensorMapFloatOOBfill);

extern "C" void kernel_launch(void* const* d_in, const int* in_sizes, int n_in,
                              void* d_out, int out_size) {
    const int*   ids   = (const int*)d_in[0];
    const int*   mask  = (const int*)d_in[1];
    const float* We    = (const float*)d_in[2];
    const float* gates = (const float*)d_in[3];
    const float* Wout  = (const float*)d_in[4];
    const float* bout  = (const float*)d_in[5];
    float* out = (float*)d_out;

    int BS    = in_sizes[0];          // 4096
    int V     = in_sizes[5];          // 32000
    int depth = in_sizes[3] / 256;    // 2
    int S     = 2048;
    int B     = BS / S;

    // Build tensor map for TMA stores (runtime-resolved driver entry point,
    // no -lcuda link dependency). Falls back to direct stores on any failure.
    CUtensorMap tmap;
    int use_tma = 0;
    {
        void* fp = nullptr;
        cudaDriverEntryPointQueryResult qr = cudaDriverEntryPointSymbolNotFound;
        if (cudaGetDriverEntryPoint("cuTensorMapEncodeTiled", &fp,
                                    cudaEnableDefault, &qr) == cudaSuccess &&
            qr == cudaDriverEntryPointSuccess && fp) {
            tmap_encode_fn enc = (tmap_encode_fn)fp;
            cuuint64_t dims[2]    = {(cuuint64_t)V, (cuuint64_t)BS};
            cuuint64_t strides[1] = {(cuuint64_t)V * 4};
            cuuint32_t box[2]     = {64, 128};
            cuuint32_t estr[2]    = {1, 1};
            CUresult r = enc(&tmap, CU_TENSOR_MAP_DATA_TYPE_FLOAT32, 2, out,
                             dims, strides, box, estr,
                             CU_TENSOR_MAP_INTERLEAVE_NONE,
                             CU_TENSOR_MAP_SWIZZLE_NONE,
                             CU_TENSOR_MAP_L2_PROMOTION_L2_128B,
                             CU_TENSOR_MAP_FLOAT_OOB_FILL_NONE);
            if (r == CUDA_SUCCESS) use_tma = 1;
        }
    }

    cudaFuncSetAttribute(hmma_gemm_kernel,
                         cudaFuncAttributeMaxDynamicSharedMemorySize, SMEM_BYTES);

    int prepBlocks  = (BS + 15) / 16;           // 256 (16 tokens per block)
    int wconvBlocks = (V + 255) / 256;          // 125
    prep_all_kernel<<<prepBlocks + wconvBlocks, 256>>>(
        ids, mask, We, gates, Wout, BS, depth, S, B, V, prepBlocks);

    dim3 grid(V / 128, BS / 128);     // (250, 32)
    hmma_gemm_kernel<<<grid, 256, SMEM_BYTES>>>(tmap, bout, out, V, use_tma);
}

// round 14
// speedup vs baseline: 1.4163x; 1.4163x over previous
#include <cuda_runtime.h>
#include <cuda_bf16.h>
#include <cstdint>

typedef unsigned long long ull;

// ---------------------------------------------------------------------------
// Stage 1 scratch (row layout, K=48 bf16 per row = 96 B):
//   g_A[m][48]: [Phi(16) | Phi(16) | Plo(16)]
//   g_W[v][48]: [Whi(16) | Wlo(16) | Whi(16)]
// D = Phi*Whi + Phi*Wlo + Plo*Whi (+ bias in epilogue); lo*lo term ~2^-18
// Stage 2 scratch (fragment-direct layout, built by frag_kernel):
//   g_Af[t][ks][lane] : uint4 = (a0,a1,a2,a3) for m16n8k16 A fragment,
//        16-row tile t, k-step ks — exactly what ldmatrix.x4 produced (R11).
//   g_Wf[p][ks][lane] : uint4 = (b0_even,b1_even,b0_odd,b1_odd) for the
//        8-col tile pair p — exactly what ldmatrix.x4 produced in R12.
// ---------------------------------------------------------------------------
__device__ __align__(16) __nv_bfloat16 g_A[4096 * 48];
__device__ __align__(16) __nv_bfloat16 g_W[32000 * 48];
__device__ __align__(16) uint4 g_Af[256 * 3 * 32];    // 384 KB
__device__ __align__(16) uint4 g_Wf[2000 * 3 * 32];   //   3 MB

__device__ __forceinline__ void bf16_split(float x, __nv_bfloat16& hi, __nv_bfloat16& lo) {
    hi = __float2bfloat16(x);
    lo = __float2bfloat16(x - __bfloat162float(hi));
}

// ---------------------------------------------------------------------------
// Kernel 1 (fused): blocks [0, prepBlocks): half-warp-per-token circuit -> g_A
//                   blocks [prepBlocks, ...): W_out conversion        -> g_W
// (unchanged from R11 — proven)
// ---------------------------------------------------------------------------
__global__ __launch_bounds__(256)
void prep_all_kernel(const int* __restrict__ ids,
                     const int* __restrict__ mask,
                     const float* __restrict__ We,
                     const float* __restrict__ gates,
                     const float* __restrict__ Wout,
                     int BS, int depth, int S, int B, int V, int prepBlocks) {
    if (blockIdx.x < (unsigned)prepBlocks) {
        __shared__ float sgt[2 * 256];   // transposed: sgt[l*256 + d*16 + o]
        for (int i = threadIdx.x; i < depth * 256; i += 256) {
            int l = i >> 8, r = i & 255, o = r >> 4, d = r & 15;
            sgt[l * 256 + d * 16 + o] = gates[i];
        }
        __syncthreads();

        int lane = threadIdx.x & 31, wid = threadIdx.x >> 5;
        int half = lane >> 4, k = lane & 15;
        int m = blockIdx.x * 16 + wid * 2 + half;
        if (m >= BS) return;

        int tok = ids[m];
        float e = We[(size_t)tok * 16 + k];
        float s = e * e;
#pragma unroll
        for (int off = 8; off; off >>= 1)
            s += __shfl_xor_sync(0xffffffffu, s, off, 16);
        e *= 1.f / (sqrtf(s) + 1e-12f);
        float st = e;

        for (int l = 0; l < depth; l++) {
            float acc = 0.f;
            const float* g = sgt + l * 256 + k;
#pragma unroll
            for (int d = 0; d < 16; d++) {
                float sd = __shfl_sync(0xffffffffu, st, d, 16);
                acc = fmaf(sd, g[d * 16], acc);
            }
            float x = acc * (0.99f * 0.99f) + (0.01f / 16.f);
            float s2 = x * x;
#pragma unroll
            for (int off = 8; off; off >>= 1)
                s2 += __shfl_xor_sync(0xffffffffu, s2, off, 16);
            st = x * (1.f / (sqrtf(s2) + 1e-12f));
        }
        st = st * 0.99f + (0.01f / 16.f);

        int s_pos = m % S;
        bool ap = true;
        for (int b = 0; b < B; b++) ap = ap && (mask[b * S + s_pos] != 0);

        float v = ap ? st : e;
        __nv_bfloat16 hi, lo; bf16_split(v, hi, lo);
        __nv_bfloat16* row = g_A + (size_t)m * 48;
        row[k] = hi; row[16 + k] = hi; row[32 + k] = lo;
    } else {
        int v = (blockIdx.x - prepBlocks) * 256 + threadIdx.x;
        if (v >= V) return;
        const float* wr = Wout + (size_t)v * 16;
        __nv_bfloat16* row = g_W + (size_t)v * 48;
#pragma unroll
        for (int k = 0; k < 16; k++) {
            __nv_bfloat16 hi, lo; bf16_split(wr[k], hi, lo);
            row[k] = hi; row[16 + k] = lo; row[32 + k] = hi;
        }
    }
}

// ---------------------------------------------------------------------------
// Kernel 1.5: row layout -> fragment-direct layout. One warp per A tile /
// W pair; lane (rr=lane>>2, cc=lane&3) gathers its 4 u32 fragment words and
// emits one coalesced STG.128. Tiny (3.4 MB reshuffle, ~2 us).
// ---------------------------------------------------------------------------
__global__ __launch_bounds__(256)
void frag_kernel(int nAtiles, int nWpairs, int wBlocksOff) {
    int wid = threadIdx.x >> 5, lane = threadIdx.x & 31;
    int rr = lane >> 2, cc = lane & 3;
    if ((int)blockIdx.x < wBlocksOff) {
        int t = blockIdx.x * 8 + wid;
        if (t >= nAtiles) return;
        const __nv_bfloat16* base = g_A + (size_t)t * 16 * 48;
#pragma unroll
        for (int ks = 0; ks < 3; ks++) {
            uint32_t x = *(const uint32_t*)(base + rr * 48 + 16 * ks + 2 * cc);
            uint32_t y = *(const uint32_t*)(base + (rr + 8) * 48 + 16 * ks + 2 * cc);
            uint32_t z = *(const uint32_t*)(base + rr * 48 + 16 * ks + 2 * cc + 8);
            uint32_t w = *(const uint32_t*)(base + (rr + 8) * 48 + 16 * ks + 2 * cc + 8);
            g_Af[(t * 3 + ks) * 32 + lane] = make_uint4(x, y, z, w);
        }
    } else {
        int p = (blockIdx.x - wBlocksOff) * 8 + wid;
        if (p >= nWpairs) return;
        const __nv_bfloat16* base = g_W + (size_t)p * 16 * 48;
#pragma unroll
        for (int ks = 0; ks < 3; ks++) {
            uint32_t x = *(const uint32_t*)(base + rr * 48 + 16 * ks + 2 * cc);        // b0_even
            uint32_t y = *(const uint32_t*)(base + rr * 48 + 16 * ks + 2 * cc + 8);    // b1_even
            uint32_t z = *(const uint32_t*)(base + (rr + 8) * 48 + 16 * ks + 2 * cc);  // b0_odd
            uint32_t w = *(const uint32_t*)(base + (rr + 8) * 48 + 16 * ks + 2 * cc + 8); // b1_odd
            g_Wf[(p * 3 + ks) * 32 + lane] = make_uint4(x, y, z, w);
        }
    }
}

// ---------------------------------------------------------------------------
// Kernel 2: HMMA bf16 GEMM, tile 128x128, 8 warps (2x4), K=48.
// SMEM-FREE mainloop: fragments arrive via coalesced LDG.128 from the
// fragment-direct scratch (L2-resident) straight into mma.sync registers.
// No STS, no ldmatrix, no __syncthreads anywhere — warps fully decoupled.
// Bias via direct per-thread LDG. Epilogue: shuffle-paired float4 streaming
// stores (R10/R11, proven).
// ---------------------------------------------------------------------------
__global__ __launch_bounds__(256, 2)
void hmma_gemm_kernel(const float* __restrict__ bout,
                      float* __restrict__ out, int V) {
    int tid = threadIdx.x, wid = tid >> 5, lane = tid & 31;
    int row0 = blockIdx.y * 128;
    int v0   = blockIdx.x * 128;
    int wm = wid >> 2;        // 0..1 : 64-row half
    int wn = wid & 3;         // 0..3 : 32-col quarter

    int tbase = (row0 >> 4) + wm * 4;   // A tiles  (t = tbase + mt)
    int pbase = (v0  >> 4) + wn * 2;    // W pairs  (p = pbase + np)

    float c[4][4][4];
#pragma unroll
    for (int mt = 0; mt < 4; mt++)
#pragma unroll
        for (int nt = 0; nt < 4; nt++)
#pragma unroll
            for (int j = 0; j < 4; j++) c[mt][nt][j] = 0.f;

#pragma unroll
    for (int ks = 0; ks < 3; ks++) {
        uint4 a[4], b[2];
#pragma unroll
        for (int mt = 0; mt < 4; mt++)
            a[mt] = __ldg(&g_Af[((tbase + mt) * 3 + ks) * 32 + lane]);
#pragma unroll
        for (int np = 0; np < 2; np++)
            b[np] = __ldg(&g_Wf[((pbase + np) * 3 + ks) * 32 + lane]);
#pragma unroll
        for (int mt = 0; mt < 4; mt++)
#pragma unroll
            for (int np = 0; np < 2; np++) {
                asm volatile(
                    "mma.sync.aligned.m16n8k16.row.col.f32.bf16.bf16.f32 "
                    "{%0,%1,%2,%3}, {%4,%5,%6,%7}, {%8,%9}, {%0,%1,%2,%3};"
                    : "+f"(c[mt][2*np][0]), "+f"(c[mt][2*np][1]),
                      "+f"(c[mt][2*np][2]), "+f"(c[mt][2*np][3])
                    : "r"(a[mt].x), "r"(a[mt].y), "r"(a[mt].z), "r"(a[mt].w),
                      "r"(b[np].x), "r"(b[np].y));
                asm volatile(
                    "mma.sync.aligned.m16n8k16.row.col.f32.bf16.bf16.f32 "
                    "{%0,%1,%2,%3}, {%4,%5,%6,%7}, {%8,%9}, {%0,%1,%2,%3};"
                    : "+f"(c[mt][2*np+1][0]), "+f"(c[mt][2*np+1][1]),
                      "+f"(c[mt][2*np+1][2]), "+f"(c[mt][2*np+1][3])
                    : "r"(a[mt].x), "r"(a[mt].y), "r"(a[mt].z), "r"(a[mt].w),
                      "r"(b[np].z), "r"(b[np].w));
            }
    }

    // bias add (direct LDG; bout region is L2-hot)
    int rr = lane >> 2;
    int q2 = (lane & 3) * 2;
#pragma unroll
    for (int nt = 0; nt < 4; nt++) {
        float2 bv = *(const float2*)(bout + v0 + wn * 32 + nt * 8 + q2);
#pragma unroll
        for (int mt = 0; mt < 4; mt++) {
            c[mt][nt][0] += bv.x; c[mt][nt][1] += bv.y;
            c[mt][nt][2] += bv.x; c[mt][nt][3] += bv.y;
        }
    }

    // ---------------- shuffle-paired epilogue (R10/R11) ----------------------
    bool evn = ((lane & 1) == 0);
#pragma unroll
    for (int mt = 0; mt < 4; mt++) {
#pragma unroll
        for (int ntp = 0; ntp < 2; ntp++) {
#pragma unroll
            for (int h2 = 0; h2 < 2; h2++) {
                float a0 = c[mt][2*ntp][h2*2],   a1 = c[mt][2*ntp][h2*2+1];
                float b0 = c[mt][2*ntp+1][h2*2], b1 = c[mt][2*ntp+1][h2*2+1];
                float ra0 = __shfl_xor_sync(0xffffffffu, a0, 1);
                float ra1 = __shfl_xor_sync(0xffffffffu, a1, 1);
                float rb0 = __shfl_xor_sync(0xffffffffu, b0, 1);
                float rb1 = __shfl_xor_sync(0xffffffffu, b1, 1);
                float4 f4;
                int colbase;
                if (evn) {
                    f4 = make_float4(a0, a1, ra0, ra1);
                    colbase = 16 * ntp + q2;
                } else {
                    f4 = make_float4(rb0, rb1, b0, b1);
                    colbase = 16 * ntp + 8 + (q2 - 2);
                }
                int grow = row0 + wm * 64 + mt * 16 + rr + h2 * 8;
                int gcol = v0 + wn * 32 + colbase;
                __stcs((float4*)(out + (size_t)grow * V + gcol), f4);
            }
        }
    }
}

// ---------------------------------------------------------------------------
// Launch
// ---------------------------------------------------------------------------
extern "C" void kernel_launch(void* const* d_in, const int* in_sizes, int n_in,
                              void* d_out, int out_size) {
    const int*   ids   = (const int*)d_in[0];
    const int*   mask  = (const int*)d_in[1];
    const float* We    = (const float*)d_in[2];
    const float* gates = (const float*)d_in[3];
    const float* Wout  = (const float*)d_in[4];
    const float* bout  = (const float*)d_in[5];
    float* out = (float*)d_out;

    int BS    = in_sizes[0];          // 4096
    int V     = in_sizes[5];          // 32000
    int depth = in_sizes[3] / 256;    // 2
    int S     = 2048;
    int B     = BS / S;

    int prepBlocks  = (BS + 15) / 16;           // 256 (16 tokens per block)
    int wconvBlocks = (V + 255) / 256;          // 125
    prep_all_kernel<<<prepBlocks + wconvBlocks, 256>>>(
        ids, mask, We, gates, Wout, BS, depth, S, B, V, prepBlocks);

    int nAtiles = BS / 16;                      // 256
    int nWpairs = V / 16;                       // 2000
    int aBlocks = (nAtiles + 7) / 8;            // 32
    int wBlocks = (nWpairs + 7) / 8;            // 250
    frag_kernel<<<aBlocks + wBlocks, 256>>>(nAtiles, nWpairs, aBlocks);

    dim3 grid(V / 128, BS / 128);     // (250, 32)
    hmma_gemm_kernel<<<grid, 256>>>(bout, out, V);
}

// round 15
// speedup vs baseline: 1.5465x; 1.0920x over previous
#include <cuda_runtime.h>
#include <cuda_bf16.h>
#include <cstdint>

typedef unsigned long long ull;

// ---------------------------------------------------------------------------
// Fragment-direct scratch. Only 2 distinct fragments per 16-row tile:
//   g_Af[t*2+0][lane] : Phi fragment (uint4 = a0..a3 of m16n8k16 A)
//   g_Af[t*2+1][lane] : Plo fragment
//   g_Wf[p*2+0][lane] : Whi fragment (uint4 = b0/b1 of the 8-col tile pair)
//   g_Wf[p*2+1][lane] : Wlo fragment
// D = Phi*Whi + Phi*Wlo + Plo*Whi (+ bias in epilogue); lo*lo term ~2^-18
// ---------------------------------------------------------------------------
__device__ __align__(16) uint4 g_Af[256 * 2 * 32];    // 256 KB
__device__ __align__(16) uint4 g_Wf[2000 * 2 * 32];   //   2 MB

__device__ __forceinline__ uint32_t pack_bf(float a, float b) {
    __nv_bfloat162 t = __floats2bfloat162_rn(a, b);   // .x = a (low half)
    return *(uint32_t*)&t;
}

// ---------------------------------------------------------------------------
// Kernel 1 (fused):
//  blocks [0, prepBlocks): one 16-token A tile per block. Half-warp-per-token
//    circuit (proven R11) -> hi/lo staged in 1KB smem -> warps 0/1 emit the
//    two A fragments directly (mapping identical to R14 frag_kernel).
//  blocks [prepBlocks, ...): warp-per-W-pair: load Wout rows, hi/lo split,
//    pack Whi/Wlo fragments, coalesced uint4 stores.
// ---------------------------------------------------------------------------
__global__ __launch_bounds__(256)
void prep_all_kernel(const int* __restrict__ ids,
                     const int* __restrict__ mask,
                     const float* __restrict__ We,
                     const float* __restrict__ gates,
                     const float* __restrict__ Wout,
                     int BS, int depth, int S, int B, int V, int prepBlocks) {
    int lane = threadIdx.x & 31, wid = threadIdx.x >> 5;
    int rr = lane >> 2, cc = lane & 3;

    if (blockIdx.x < (unsigned)prepBlocks) {
        __shared__ float sgt[2 * 256];            // transposed gates
        __shared__ __nv_bfloat16 s_hi[16 * 16];   // [token][k]
        __shared__ __nv_bfloat16 s_lo[16 * 16];
        for (int i = threadIdx.x; i < depth * 256; i += 256) {
            int l = i >> 8, r = i & 255, o = r >> 4, d = r & 15;
            sgt[l * 256 + d * 16 + o] = gates[i];
        }
        __syncthreads();

        int half = lane >> 4, k = lane & 15;
        int tok_local = wid * 2 + half;
        int m = blockIdx.x * 16 + tok_local;

        int tok = ids[m];
        float e = We[(size_t)tok * 16 + k];
        float s = e * e;
#pragma unroll
        for (int off = 8; off; off >>= 1)
            s += __shfl_xor_sync(0xffffffffu, s, off, 16);
        e *= 1.f / (sqrtf(s) + 1e-12f);
        float st = e;

        for (int l = 0; l < depth; l++) {
            float acc = 0.f;
            const float* g = sgt + l * 256 + k;
#pragma unroll
            for (int d = 0; d < 16; d++) {
                float sd = __shfl_sync(0xffffffffu, st, d, 16);
                acc = fmaf(sd, g[d * 16], acc);
            }
            float x = acc * (0.99f * 0.99f) + (0.01f / 16.f);
            float s2 = x * x;
#pragma unroll
            for (int off = 8; off; off >>= 1)
                s2 += __shfl_xor_sync(0xffffffffu, s2, off, 16);
            st = x * (1.f / (sqrtf(s2) + 1e-12f));
        }
        st = st * 0.99f + (0.01f / 16.f);

        int s_pos = m % S;
        bool ap = true;
        for (int b = 0; b < B; b++) ap = ap && (mask[b * S + s_pos] != 0);

        float v = ap ? st : e;
        __nv_bfloat16 hi = __float2bfloat16(v);
        __nv_bfloat16 lo = __float2bfloat16(v - __bfloat162float(hi));
        s_hi[tok_local * 16 + k] = hi;
        s_lo[tok_local * 16 + k] = lo;
        __syncthreads();

        // warps 0/1 gather the two fragments (mapping == R14 frag_kernel):
        //   x = [rr][2cc], y = [rr+8][2cc], z = [rr][2cc+8], w = [rr+8][2cc+8]
        if (wid < 2) {
            const __nv_bfloat16* src = (wid == 0) ? s_hi : s_lo;
            uint32_t x = *(const uint32_t*)(src + rr * 16 + 2 * cc);
            uint32_t y = *(const uint32_t*)(src + (rr + 8) * 16 + 2 * cc);
            uint32_t z = *(const uint32_t*)(src + rr * 16 + 2 * cc + 8);
            uint32_t w = *(const uint32_t*)(src + (rr + 8) * 16 + 2 * cc + 8);
            g_Af[(blockIdx.x * 2 + wid) * 32 + lane] = make_uint4(x, y, z, w);
        }
    } else {
        // W pair p: 16 vocab rows. Lane needs rows v0+rr, v0+rr+8,
        // cols {2cc,2cc+1} and {2cc+8,2cc+9}.
        int p = (blockIdx.x - prepBlocks) * 8 + wid;
        int nPairs = V >> 4;
        if (p >= nPairs) return;
        const float* base = Wout + (size_t)p * 16 * 16;
        float2 w00 = *(const float2*)(base + rr * 16 + 2 * cc);
        float2 w01 = *(const float2*)(base + rr * 16 + 2 * cc + 8);
        float2 w10 = *(const float2*)(base + (rr + 8) * 16 + 2 * cc);
        float2 w11 = *(const float2*)(base + (rr + 8) * 16 + 2 * cc + 8);

        // hi parts (round-to-nearest bf16) and lo residuals
        float h00x = __bfloat162float(__float2bfloat16(w00.x));
        float h00y = __bfloat162float(__float2bfloat16(w00.y));
        float h01x = __bfloat162float(__float2bfloat16(w01.x));
        float h01y = __bfloat162float(__float2bfloat16(w01.y));
        float h10x = __bfloat162float(__float2bfloat16(w10.x));
        float h10y = __bfloat162float(__float2bfloat16(w10.y));
        float h11x = __bfloat162float(__float2bfloat16(w11.x));
        float h11y = __bfloat162float(__float2bfloat16(w11.y));

        // B fragment order (== R14): x = row rr cols 2cc, y = row rr cols 2cc+8,
        //                            z = row rr+8 cols 2cc, w = row rr+8 cols 2cc+8
        uint4 bh = make_uint4(pack_bf(h00x, h00y), pack_bf(h01x, h01y),
                              pack_bf(h10x, h10y), pack_bf(h11x, h11y));
        uint4 bl = make_uint4(pack_bf(w00.x - h00x, w00.y - h00y),
                              pack_bf(w01.x - h01x, w01.y - h01y),
                              pack_bf(w10.x - h10x, w10.y - h10y),
                              pack_bf(w11.x - h11x, w11.y - h11y));
        g_Wf[(p * 2 + 0) * 32 + lane] = bh;
        g_Wf[(p * 2 + 1) * 32 + lane] = bl;
    }
}

// ---------------------------------------------------------------------------
// Kernel 2: HMMA bf16 GEMM, tile 128x128, 8 warps (2x4). SMEM-free, sync-free
// (R14, proven). Dedup fragments: 12 LDG.128/warp (was 18). Three phases:
//   Phi*Whi, Phi*Wlo, Plo*Whi  (48 MMAs total, unchanged).
// Bias via direct LDG; shuffle-paired float4 streaming stores (R10/R11).
// ---------------------------------------------------------------------------
__global__ __launch_bounds__(256, 2)
void hmma_gemm_kernel(const float* __restrict__ bout,
                      float* __restrict__ out, int V) {
    int tid = threadIdx.x, wid = tid >> 5, lane = tid & 31;
    int row0 = blockIdx.y * 128;
    int v0   = blockIdx.x * 128;
    int wm = wid >> 2;        // 0..1 : 64-row half
    int wn = wid & 3;         // 0..3 : 32-col quarter

    int tbase = (row0 >> 4) + wm * 4;   // A tiles  (t = tbase + mt)
    int pbase = (v0  >> 4) + wn * 2;    // W pairs  (p = pbase + np)

    float c[4][4][4];
#pragma unroll
    for (int mt = 0; mt < 4; mt++)
#pragma unroll
        for (int nt = 0; nt < 4; nt++)
#pragma unroll
            for (int j = 0; j < 4; j++) c[mt][nt][j] = 0.f;

#define MMA8(acc, A, B0, B1)                                                  \
    asm volatile(                                                             \
        "mma.sync.aligned.m16n8k16.row.col.f32.bf16.bf16.f32 "                \
        "{%0,%1,%2,%3}, {%4,%5,%6,%7}, {%8,%9}, {%0,%1,%2,%3};"               \
        : "+f"((acc)[0]), "+f"((acc)[1]), "+f"((acc)[2]), "+f"((acc)[3])      \
        : "r"((A).x), "r"((A).y), "r"((A).z), "r"((A).w), "r"(B0), "r"(B1))

    {
        uint4 a01[4], bh[2];
#pragma unroll
        for (int mt = 0; mt < 4; mt++)
            a01[mt] = __ldg(&g_Af[((tbase + mt) * 2 + 0) * 32 + lane]);
#pragma unroll
        for (int np = 0; np < 2; np++)
            bh[np] = __ldg(&g_Wf[((pbase + np) * 2 + 0) * 32 + lane]);

        // phase 1: Phi * Whi
#pragma unroll
        for (int mt = 0; mt < 4; mt++)
#pragma unroll
            for (int np = 0; np < 2; np++) {
                MMA8(c[mt][2*np],   a01[mt], bh[np].x, bh[np].y);
                MMA8(c[mt][2*np+1], a01[mt], bh[np].z, bh[np].w);
            }

        // phase 2: Phi * Wlo
        {
            uint4 bl[2];
#pragma unroll
            for (int np = 0; np < 2; np++)
                bl[np] = __ldg(&g_Wf[((pbase + np) * 2 + 1) * 32 + lane]);
#pragma unroll
            for (int mt = 0; mt < 4; mt++)
#pragma unroll
                for (int np = 0; np < 2; np++) {
                    MMA8(c[mt][2*np],   a01[mt], bl[np].x, bl[np].y);
                    MMA8(c[mt][2*np+1], a01[mt], bl[np].z, bl[np].w);
                }
        }

        // phase 3: Plo * Whi  (a01 dead; reuse its registers for a2)
#pragma unroll
        for (int mt = 0; mt < 4; mt++)
            a01[mt] = __ldg(&g_Af[((tbase + mt) * 2 + 1) * 32 + lane]);
#pragma unroll
        for (int mt = 0; mt < 4; mt++)
#pragma unroll
            for (int np = 0; np < 2; np++) {
                MMA8(c[mt][2*np],   a01[mt], bh[np].x, bh[np].y);
                MMA8(c[mt][2*np+1], a01[mt], bh[np].z, bh[np].w);
            }
    }

    // bias add (direct LDG; bout region is L2-hot)
    int rr = lane >> 2;
    int q2 = (lane & 3) * 2;
#pragma unroll
    for (int nt = 0; nt < 4; nt++) {
        float2 bv = *(const float2*)(bout + v0 + wn * 32 + nt * 8 + q2);
#pragma unroll
        for (int mt = 0; mt < 4; mt++) {
            c[mt][nt][0] += bv.x; c[mt][nt][1] += bv.y;
            c[mt][nt][2] += bv.x; c[mt][nt][3] += bv.y;
        }
    }

    // ---------------- shuffle-paired epilogue (R10/R11) ----------------------
    bool evn = ((lane & 1) == 0);
#pragma unroll
    for (int mt = 0; mt < 4; mt++) {
#pragma unroll
        for (int ntp = 0; ntp < 2; ntp++) {
#pragma unroll
            for (int h2 = 0; h2 < 2; h2++) {
                float a0 = c[mt][2*ntp][h2*2],   a1 = c[mt][2*ntp][h2*2+1];
                float b0 = c[mt][2*ntp+1][h2*2], b1 = c[mt][2*ntp+1][h2*2+1];
                float ra0 = __shfl_xor_sync(0xffffffffu, a0, 1);
                float ra1 = __shfl_xor_sync(0xffffffffu, a1, 1);
                float rb0 = __shfl_xor_sync(0xffffffffu, b0, 1);
                float rb1 = __shfl_xor_sync(0xffffffffu, b1, 1);
                float4 f4;
                int colbase;
                if (evn) {
                    f4 = make_float4(a0, a1, ra0, ra1);
                    colbase = 16 * ntp + q2;
                } else {
                    f4 = make_float4(rb0, rb1, b0, b1);
                    colbase = 16 * ntp + 8 + (q2 - 2);
                }
                int grow = row0 + wm * 64 + mt * 16 + rr + h2 * 8;
                int gcol = v0 + wn * 32 + colbase;
                __stcs((float4*)(out + (size_t)grow * V + gcol), f4);
            }
        }
    }
}

// ---------------------------------------------------------------------------
// Launch
// ---------------------------------------------------------------------------
extern "C" void kernel_launch(void* const* d_in, const int* in_sizes, int n_in,
                              void* d_out, int out_size) {
    const int*   ids   = (const int*)d_in[0];
    const int*   mask  = (const int*)d_in[1];
    const float* We    = (const float*)d_in[2];
    const float* gates = (const float*)d_in[3];
    const float* Wout  = (const float*)d_in[4];
    const float* bout  = (const float*)d_in[5];
    float* out = (float*)d_out;

    int BS    = in_sizes[0];          // 4096
    int V     = in_sizes[5];          // 32000
    int depth = in_sizes[3] / 256;    // 2
    int S     = 2048;
    int B     = BS / S;

    int prepBlocks  = BS / 16;                  // 256 (one A tile per block)
    int wconvBlocks = (V / 16 + 7) / 8;         // 250 (8 W pairs per block)
    prep_all_kernel<<<prepBlocks + wconvBlocks, 256>>>(
        ids, mask, We, gates, Wout, BS, depth, S, B, V, prepBlocks);

    dim3 grid(V / 128, BS / 128);     // (250, 32)
    hmma_gemm_kernel<<<grid, 256>>>(bout, out, V);
}

// round 16
// speedup vs baseline: 1.6854x; 1.0898x over previous
#include <cuda_runtime.h>
#include <cuda_bf16.h>
#include <cstdint>

typedef unsigned long long ull;

// ---------------------------------------------------------------------------
// Fragment-direct scratch. Only 2 distinct fragments per 16-row tile:
//   g_Af[t*2+0][lane] : Phi fragment (uint4 = a0..a3 of m16n8k16 A)
//   g_Af[t*2+1][lane] : Plo fragment
//   g_Wf[p*2+0][lane] : Whi fragment (uint4 = b0/b1 of the 8-col tile pair)
//   g_Wf[p*2+1][lane] : Wlo fragment
// D = Phi*Whi + Phi*Wlo + Plo*Whi (+ bias in epilogue); lo*lo term ~2^-18
// ---------------------------------------------------------------------------
__device__ __align__(16) uint4 g_Af[256 * 2 * 32];    // 256 KB
__device__ __align__(16) uint4 g_Wf[2000 * 2 * 32];   //   2 MB

__device__ __forceinline__ uint32_t pack_bf(float a, float b) {
    __nv_bfloat162 t = __floats2bfloat162_rn(a, b);   // .x = a (low half)
    return *(uint32_t*)&t;
}

// ---------------------------------------------------------------------------
// Kernel 1 (fused, unchanged from R15 — proven):
//  blocks [0, prepBlocks): one 16-token A tile per block -> A fragments
//  blocks [prepBlocks, ...): warp-per-W-pair -> Whi/Wlo fragments
// ---------------------------------------------------------------------------
__global__ __launch_bounds__(256)
void prep_all_kernel(const int* __restrict__ ids,
                     const int* __restrict__ mask,
                     const float* __restrict__ We,
                     const float* __restrict__ gates,
                     const float* __restrict__ Wout,
                     int BS, int depth, int S, int B, int V, int prepBlocks) {
    int lane = threadIdx.x & 31, wid = threadIdx.x >> 5;
    int rr = lane >> 2, cc = lane & 3;

    if (blockIdx.x < (unsigned)prepBlocks) {
        __shared__ float sgt[2 * 256];            // transposed gates
        __shared__ __nv_bfloat16 s_hi[16 * 16];   // [token][k]
        __shared__ __nv_bfloat16 s_lo[16 * 16];
        for (int i = threadIdx.x; i < depth * 256; i += 256) {
            int l = i >> 8, r = i & 255, o = r >> 4, d = r & 15;
            sgt[l * 256 + d * 16 + o] = gates[i];
        }
        __syncthreads();

        int half = lane >> 4, k = lane & 15;
        int tok_local = wid * 2 + half;
        int m = blockIdx.x * 16 + tok_local;

        int tok = ids[m];
        float e = We[(size_t)tok * 16 + k];
        float s = e * e;
#pragma unroll
        for (int off = 8; off; off >>= 1)
            s += __shfl_xor_sync(0xffffffffu, s, off, 16);
        e *= 1.f / (sqrtf(s) + 1e-12f);
        float st = e;

        for (int l = 0; l < depth; l++) {
            float acc = 0.f;
            const float* g = sgt + l * 256 + k;
#pragma unroll
            for (int d = 0; d < 16; d++) {
                float sd = __shfl_sync(0xffffffffu, st, d, 16);
                acc = fmaf(sd, g[d * 16], acc);
            }
            float x = acc * (0.99f * 0.99f) + (0.01f / 16.f);
            float s2 = x * x;
#pragma unroll
            for (int off = 8; off; off >>= 1)
                s2 += __shfl_xor_sync(0xffffffffu, s2, off, 16);
            st = x * (1.f / (sqrtf(s2) + 1e-12f));
        }
        st = st * 0.99f + (0.01f / 16.f);

        int s_pos = m % S;
        bool ap = true;
        for (int b = 0; b < B; b++) ap = ap && (mask[b * S + s_pos] != 0);

        float v = ap ? st : e;
        __nv_bfloat16 hi = __float2bfloat16(v);
        __nv_bfloat16 lo = __float2bfloat16(v - __bfloat162float(hi));
        s_hi[tok_local * 16 + k] = hi;
        s_lo[tok_local * 16 + k] = lo;
        __syncthreads();

        if (wid < 2) {
            const __nv_bfloat16* src = (wid == 0) ? s_hi : s_lo;
            uint32_t x = *(const uint32_t*)(src + rr * 16 + 2 * cc);
            uint32_t y = *(const uint32_t*)(src + (rr + 8) * 16 + 2 * cc);
            uint32_t z = *(const uint32_t*)(src + rr * 16 + 2 * cc + 8);
            uint32_t w = *(const uint32_t*)(src + (rr + 8) * 16 + 2 * cc + 8);
            g_Af[(blockIdx.x * 2 + wid) * 32 + lane] = make_uint4(x, y, z, w);
        }
    } else {
        int p = (blockIdx.x - prepBlocks) * 8 + wid;
        int nPairs = V >> 4;
        if (p >= nPairs) return;
        const float* base = Wout + (size_t)p * 16 * 16;
        float2 w00 = *(const float2*)(base + rr * 16 + 2 * cc);
        float2 w01 = *(const float2*)(base + rr * 16 + 2 * cc + 8);
        float2 w10 = *(const float2*)(base + (rr + 8) * 16 + 2 * cc);
        float2 w11 = *(const float2*)(base + (rr + 8) * 16 + 2 * cc + 8);

        float h00x = __bfloat162float(__float2bfloat16(w00.x));
        float h00y = __bfloat162float(__float2bfloat16(w00.y));
        float h01x = __bfloat162float(__float2bfloat16(w01.x));
        float h01y = __bfloat162float(__float2bfloat16(w01.y));
        float h10x = __bfloat162float(__float2bfloat16(w10.x));
        float h10y = __bfloat162float(__float2bfloat16(w10.y));
        float h11x = __bfloat162float(__float2bfloat16(w11.x));
        float h11y = __bfloat162float(__float2bfloat16(w11.y));

        uint4 bh = make_uint4(pack_bf(h00x, h00y), pack_bf(h01x, h01y),
                              pack_bf(h10x, h10y), pack_bf(h11x, h11y));
        uint4 bl = make_uint4(pack_bf(w00.x - h00x, w00.y - h00y),
                              pack_bf(w01.x - h01x, w01.y - h01y),
                              pack_bf(w10.x - h10x, w10.y - h10y),
                              pack_bf(w11.x - h11x, w11.y - h11y));
        g_Wf[(p * 2 + 0) * 32 + lane] = bh;
        g_Wf[(p * 2 + 1) * 32 + lane] = bl;
    }
}

// ---------------------------------------------------------------------------
// Kernel 2: HMMA bf16 GEMM, tile 128x128, 8 warps (2x4). SMEM-free, sync-free.
// STREAMING-MT restructure: W fragments + bias resident; per 16-row A tile
// (unroll-1 loop): 2 A fragment LDGs -> 12 MMAs -> bias -> shuffle-paired
// stores for that tile. Live accumulators 64->16 regs => 3 CTAs/SM; stores
// interleave with compute across the whole kernel instead of tail-bursting.
// ---------------------------------------------------------------------------
__global__ __launch_bounds__(256, 3)
void hmma_gemm_kernel(const float* __restrict__ bout,
                      float* __restrict__ out, int V) {
    int tid = threadIdx.x, wid = tid >> 5, lane = tid & 31;
    int row0 = blockIdx.y * 128;
    int v0   = blockIdx.x * 128;
    int wm = wid >> 2;        // 0..1 : 64-row half
    int wn = wid & 3;         // 0..3 : 32-col quarter

    int tbase = (row0 >> 4) + wm * 4;   // A tiles  (t = tbase + mt)
    int pbase = (v0  >> 4) + wn * 2;    // W pairs  (p = pbase + np)

    int rr = lane >> 2;
    int q2 = (lane & 3) * 2;
    bool evn = ((lane & 1) == 0);

#define MMA8(acc, A, B0, B1)                                                  \
    asm volatile(                                                             \
        "mma.sync.aligned.m16n8k16.row.col.f32.bf16.bf16.f32 "                \
        "{%0,%1,%2,%3}, {%4,%5,%6,%7}, {%8,%9}, {%0,%1,%2,%3};"               \
        : "+f"((acc)[0]), "+f"((acc)[1]), "+f"((acc)[2]), "+f"((acc)[3])      \
        : "r"((A).x), "r"((A).y), "r"((A).z), "r"((A).w), "r"(B0), "r"(B1))

    // resident W fragments + bias
    uint4 bh[2], bl[2];
#pragma unroll
    for (int np = 0; np < 2; np++) {
        bh[np] = __ldg(&g_Wf[((pbase + np) * 2 + 0) * 32 + lane]);
        bl[np] = __ldg(&g_Wf[((pbase + np) * 2 + 1) * 32 + lane]);
    }
    float2 bv[4];
#pragma unroll
    for (int nt = 0; nt < 4; nt++)
        bv[nt] = *(const float2*)(bout + v0 + wn * 32 + nt * 8 + q2);

#pragma unroll 1
    for (int mt = 0; mt < 4; mt++) {
        uint4 a01 = __ldg(&g_Af[((tbase + mt) * 2 + 0) * 32 + lane]);
        uint4 a2  = __ldg(&g_Af[((tbase + mt) * 2 + 1) * 32 + lane]);

        float c[4][4];
#pragma unroll
        for (int nt = 0; nt < 4; nt++)
#pragma unroll
            for (int j = 0; j < 4; j++) c[nt][j] = 0.f;

#pragma unroll
        for (int np = 0; np < 2; np++) {
            MMA8(c[2*np],   a01, bh[np].x, bh[np].y);
            MMA8(c[2*np+1], a01, bh[np].z, bh[np].w);
            MMA8(c[2*np],   a01, bl[np].x, bl[np].y);
            MMA8(c[2*np+1], a01, bl[np].z, bl[np].w);
            MMA8(c[2*np],   a2,  bh[np].x, bh[np].y);
            MMA8(c[2*np+1], a2,  bh[np].z, bh[np].w);
        }

        // bias
#pragma unroll
        for (int nt = 0; nt < 4; nt++) {
            c[nt][0] += bv[nt].x; c[nt][1] += bv[nt].y;
            c[nt][2] += bv[nt].x; c[nt][3] += bv[nt].y;
        }

        // shuffle-paired stores for this 16-row tile (R10/R11 pattern)
#pragma unroll
        for (int ntp = 0; ntp < 2; ntp++) {
#pragma unroll
            for (int h2 = 0; h2 < 2; h2++) {
                float a0 = c[2*ntp][h2*2],   a1 = c[2*ntp][h2*2+1];
                float b0 = c[2*ntp+1][h2*2], b1 = c[2*ntp+1][h2*2+1];
                float ra0 = __shfl_xor_sync(0xffffffffu, a0, 1);
                float ra1 = __shfl_xor_sync(0xffffffffu, a1, 1);
                float rb0 = __shfl_xor_sync(0xffffffffu, b0, 1);
                float rb1 = __shfl_xor_sync(0xffffffffu, b1, 1);
                float4 f4;
                int colbase;
                if (evn) {
                    f4 = make_float4(a0, a1, ra0, ra1);
                    colbase = 16 * ntp + q2;
                } else {
                    f4 = make_float4(rb0, rb1, b0, b1);
                    colbase = 16 * ntp + 8 + (q2 - 2);
                }
                int grow = row0 + wm * 64 + mt * 16 + rr + h2 * 8;
                int gcol = v0 + wn * 32 + colbase;
                __stcs((float4*)(out + (size_t)grow * V + gcol), f4);
            }
        }
    }
}

// ---------------------------------------------------------------------------
// Launch
// ---------------------------------------------------------------------------
extern "C" void kernel_launch(void* const* d_in, const int* in_sizes, int n_in,
                              void* d_out, int out_size) {
    const int*   ids   = (const int*)d_in[0];
    const int*   mask  = (const int*)d_in[1];
    const float* We    = (const float*)d_in[2];
    const float* gates = (const float*)d_in[3];
    const float* Wout  = (const float*)d_in[4];
    const float* bout  = (const float*)d_in[5];
    float* out = (float*)d_out;

    int BS    = in_sizes[0];          // 4096
    int V     = in_sizes[5];          // 32000
    int depth = in_sizes[3] / 256;    // 2
    int S     = 2048;
    int B     = BS / S;

    int prepBlocks  = BS / 16;                  // 256 (one A tile per block)
    int wconvBlocks = (V / 16 + 7) / 8;         // 250 (8 W pairs per block)
    prep_all_kernel<<<prepBlocks + wconvBlocks, 256>>>(
        ids, mask, We, gates, Wout, BS, depth, S, B, V, prepBlocks);

    dim3 grid(V / 128, BS / 128);     // (250, 32)
    hmma_gemm_kernel<<<grid, 256>>>(bout, out, V);
}

// round 17
// speedup vs baseline: 1.6919x; 1.0039x over previous
#include <cuda_runtime.h>
#include <cuda_bf16.h>
#include <cstdint>

typedef unsigned long long ull;

// ---------------------------------------------------------------------------
// Fragment-direct scratch. Only 2 distinct fragments per 16-row tile:
//   g_Af[t*2+0][lane] : Phi fragment (uint4 = a0..a3 of m16n8k16 A)
//   g_Af[t*2+1][lane] : Plo fragment
//   g_Wf[p*2+0][lane] : Whi fragment (uint4 = b0/b1 of the 8-col tile pair)
//   g_Wf[p*2+1][lane] : Wlo fragment
// D = Phi*Whi + Phi*Wlo + Plo*Whi (+ bias in accumulator init); lo*lo ~2^-18
// ---------------------------------------------------------------------------
__device__ __align__(16) uint4 g_Af[256 * 2 * 32];    // 256 KB
__device__ __align__(16) uint4 g_Wf[2000 * 2 * 32];   //   2 MB

__device__ __forceinline__ uint32_t pack_bf(float a, float b) {
    __nv_bfloat162 t = __floats2bfloat162_rn(a, b);   // .x = a (low half)
    return *(uint32_t*)&t;
}

// ---------------------------------------------------------------------------
// Kernel 1 (fused, unchanged from R15/R16 — proven):
//  blocks [0, prepBlocks): one 16-token A tile per block -> A fragments
//  blocks [prepBlocks, ...): warp-per-W-pair -> Whi/Wlo fragments
// ---------------------------------------------------------------------------
__global__ __launch_bounds__(256)
void prep_all_kernel(const int* __restrict__ ids,
                     const int* __restrict__ mask,
                     const float* __restrict__ We,
                     const float* __restrict__ gates,
                     const float* __restrict__ Wout,
                     int BS, int depth, int S, int B, int V, int prepBlocks) {
    int lane = threadIdx.x & 31, wid = threadIdx.x >> 5;
    int rr = lane >> 2, cc = lane & 3;

    if (blockIdx.x < (unsigned)prepBlocks) {
        __shared__ float sgt[2 * 256];            // transposed gates
        __shared__ __nv_bfloat16 s_hi[16 * 16];   // [token][k]
        __shared__ __nv_bfloat16 s_lo[16 * 16];
        for (int i = threadIdx.x; i < depth * 256; i += 256) {
            int l = i >> 8, r = i & 255, o = r >> 4, d = r & 15;
            sgt[l * 256 + d * 16 + o] = gates[i];
        }
        __syncthreads();

        int half = lane >> 4, k = lane & 15;
        int tok_local = wid * 2 + half;
        int m = blockIdx.x * 16 + tok_local;

        int tok = ids[m];
        float e = We[(size_t)tok * 16 + k];
        float s = e * e;
#pragma unroll
        for (int off = 8; off; off >>= 1)
            s += __shfl_xor_sync(0xffffffffu, s, off, 16);
        e *= 1.f / (sqrtf(s) + 1e-12f);
        float st = e;

        for (int l = 0; l < depth; l++) {
            float acc = 0.f;
            const float* g = sgt + l * 256 + k;
#pragma unroll
            for (int d = 0; d < 16; d++) {
                float sd = __shfl_sync(0xffffffffu, st, d, 16);
                acc = fmaf(sd, g[d * 16], acc);
            }
            float x = acc * (0.99f * 0.99f) + (0.01f / 16.f);
            float s2 = x * x;
#pragma unroll
            for (int off = 8; off; off >>= 1)
                s2 += __shfl_xor_sync(0xffffffffu, s2, off, 16);
            st = x * (1.f / (sqrtf(s2) + 1e-12f));
        }
        st = st * 0.99f + (0.01f / 16.f);

        int s_pos = m % S;
        bool ap = true;
        for (int b = 0; b < B; b++) ap = ap && (mask[b * S + s_pos] != 0);

        float v = ap ? st : e;
        __nv_bfloat16 hi = __float2bfloat16(v);
        __nv_bfloat16 lo = __float2bfloat16(v - __bfloat162float(hi));
        s_hi[tok_local * 16 + k] = hi;
        s_lo[tok_local * 16 + k] = lo;
        __syncthreads();

        if (wid < 2) {
            const __nv_bfloat16* src = (wid == 0) ? s_hi : s_lo;
            uint32_t x = *(const uint32_t*)(src + rr * 16 + 2 * cc);
            uint32_t y = *(const uint32_t*)(src + (rr + 8) * 16 + 2 * cc);
            uint32_t z = *(const uint32_t*)(src + rr * 16 + 2 * cc + 8);
            uint32_t w = *(const uint32_t*)(src + (rr + 8) * 16 + 2 * cc + 8);
            g_Af[(blockIdx.x * 2 + wid) * 32 + lane] = make_uint4(x, y, z, w);
        }
    } else {
        int p = (blockIdx.x - prepBlocks) * 8 + wid;
        int nPairs = V >> 4;
        if (p >= nPairs) return;
        const float* base = Wout + (size_t)p * 16 * 16;
        float2 w00 = *(const float2*)(base + rr * 16 + 2 * cc);
        float2 w01 = *(const float2*)(base + rr * 16 + 2 * cc + 8);
        float2 w10 = *(const float2*)(base + (rr + 8) * 16 + 2 * cc);
        float2 w11 = *(const float2*)(base + (rr + 8) * 16 + 2 * cc + 8);

        float h00x = __bfloat162float(__float2bfloat16(w00.x));
        float h00y = __bfloat162float(__float2bfloat16(w00.y));
        float h01x = __bfloat162float(__float2bfloat16(w01.x));
        float h01y = __bfloat162float(__float2bfloat16(w01.y));
        float h10x = __bfloat162float(__float2bfloat16(w10.x));
        float h10y = __bfloat162float(__float2bfloat16(w10.y));
        float h11x = __bfloat162float(__float2bfloat16(w11.x));
        float h11y = __bfloat162float(__float2bfloat16(w11.y));

        uint4 bh = make_uint4(pack_bf(h00x, h00y), pack_bf(h01x, h01y),
                              pack_bf(h10x, h10y), pack_bf(h11x, h11y));
        uint4 bl = make_uint4(pack_bf(w00.x - h00x, w00.y - h00y),
                              pack_bf(w01.x - h01x, w01.y - h01y),
                              pack_bf(w10.x - h10x, w10.y - h10y),
                              pack_bf(w11.x - h11x, w11.y - h11y));
        g_Wf[(p * 2 + 0) * 32 + lane] = bh;
        g_Wf[(p * 2 + 1) * 32 + lane] = bl;
    }
}

// ---------------------------------------------------------------------------
// Kernel 2: HMMA bf16 GEMM, tile 128x128, 8 warps (2x4). SMEM-free, sync-free,
// streaming-mt (R16, proven). This round: (a) double-buffered prefetch of the
// next tile's A fragments so LDG latency hides under the current tile's MMAs
// and stores; (b) bias folded into accumulator init (FADDs deleted).
// ---------------------------------------------------------------------------
__global__ __launch_bounds__(256, 3)
void hmma_gemm_kernel(const float* __restrict__ bout,
                      float* __restrict__ out, int V) {
    int tid = threadIdx.x, wid = tid >> 5, lane = tid & 31;
    int row0 = blockIdx.y * 128;
    int v0   = blockIdx.x * 128;
    int wm = wid >> 2;        // 0..1 : 64-row half
    int wn = wid & 3;         // 0..3 : 32-col quarter

    int tbase = (row0 >> 4) + wm * 4;   // A tiles  (t = tbase + mt)
    int pbase = (v0  >> 4) + wn * 2;    // W pairs  (p = pbase + np)

    int rr = lane >> 2;
    int q2 = (lane & 3) * 2;
    bool evn = ((lane & 1) == 0);

#define MMA8(acc, A, B0, B1)                                                  \
    asm volatile(                                                             \
        "mma.sync.aligned.m16n8k16.row.col.f32.bf16.bf16.f32 "                \
        "{%0,%1,%2,%3}, {%4,%5,%6,%7}, {%8,%9}, {%0,%1,%2,%3};"               \
        : "+f"((acc)[0]), "+f"((acc)[1]), "+f"((acc)[2]), "+f"((acc)[3])      \
        : "r"((A).x), "r"((A).y), "r"((A).z), "r"((A).w), "r"(B0), "r"(B1))

    // resident W fragments + bias
    uint4 bh[2], bl[2];
#pragma unroll
    for (int np = 0; np < 2; np++) {
        bh[np] = __ldg(&g_Wf[((pbase + np) * 2 + 0) * 32 + lane]);
        bl[np] = __ldg(&g_Wf[((pbase + np) * 2 + 1) * 32 + lane]);
    }
    float2 bv[4];
#pragma unroll
    for (int nt = 0; nt < 4; nt++)
        bv[nt] = *(const float2*)(bout + v0 + wn * 32 + nt * 8 + q2);

    // preload tile 0's A fragments
    uint4 a01 = __ldg(&g_Af[(tbase * 2 + 0) * 32 + lane]);
    uint4 a2  = __ldg(&g_Af[(tbase * 2 + 1) * 32 + lane]);

#pragma unroll 1
    for (int mt = 0; mt < 4; mt++) {
        // prefetch next tile's A fragments (hidden under MMAs + stores)
        uint4 na01, na2;
        if (mt < 3) {
            na01 = __ldg(&g_Af[((tbase + mt + 1) * 2 + 0) * 32 + lane]);
            na2  = __ldg(&g_Af[((tbase + mt + 1) * 2 + 1) * 32 + lane]);
        }

        // accumulators initialized with bias (rows rr and rr+8 share bias)
        float c[4][4];
#pragma unroll
        for (int nt = 0; nt < 4; nt++) {
            c[nt][0] = bv[nt].x; c[nt][1] = bv[nt].y;
            c[nt][2] = bv[nt].x; c[nt][3] = bv[nt].y;
        }

#pragma unroll
        for (int np = 0; np < 2; np++) {
            MMA8(c[2*np],   a01, bh[np].x, bh[np].y);
            MMA8(c[2*np+1], a01, bh[np].z, bh[np].w);
            MMA8(c[2*np],   a01, bl[np].x, bl[np].y);
            MMA8(c[2*np+1], a01, bl[np].z, bl[np].w);
            MMA8(c[2*np],   a2,  bh[np].x, bh[np].y);
            MMA8(c[2*np+1], a2,  bh[np].z, bh[np].w);
        }

        // shuffle-paired stores for this 16-row tile (R10/R11 pattern)
#pragma unroll
        for (int ntp = 0; ntp < 2; ntp++) {
#pragma unroll
            for (int h2 = 0; h2 < 2; h2++) {
                float a0 = c[2*ntp][h2*2],   a1 = c[2*ntp][h2*2+1];
                float b0 = c[2*ntp+1][h2*2], b1 = c[2*ntp+1][h2*2+1];
                float ra0 = __shfl_xor_sync(0xffffffffu, a0, 1);
                float ra1 = __shfl_xor_sync(0xffffffffu, a1, 1);
                float rb0 = __shfl_xor_sync(0xffffffffu, b0, 1);
                float rb1 = __shfl_xor_sync(0xffffffffu, b1, 1);
                float4 f4;
                int colbase;
                if (evn) {
                    f4 = make_float4(a0, a1, ra0, ra1);
                    colbase = 16 * ntp + q2;
                } else {
                    f4 = make_float4(rb0, rb1, b0, b1);
                    colbase = 16 * ntp + 8 + (q2 - 2);
                }
                int grow = row0 + wm * 64 + mt * 16 + rr + h2 * 8;
                int gcol = v0 + wn * 32 + colbase;
                __stcs((float4*)(out + (size_t)grow * V + gcol), f4);
            }
        }

        a01 = na01;
        a2  = na2;
    }
}

// ---------------------------------------------------------------------------
// Launch
// ---------------------------------------------------------------------------
extern "C" void kernel_launch(void* const* d_in, const int* in_sizes, int n_in,
                              void* d_out, int out_size) {
    const int*   ids   = (const int*)d_in[0];
    const int*   mask  = (const int*)d_in[1];
    const float* We    = (const float*)d_in[2];
    const float* gates = (const float*)d_in[3];
    const float* Wout  = (const float*)d_in[4];
    const float* bout  = (const float*)d_in[5];
    float* out = (float*)d_out;

    int BS    = in_sizes[0];          // 4096
    int V     = in_sizes[5];          // 32000
    int depth = in_sizes[3] / 256;    // 2
    int S     = 2048;
    int B     = BS / S;

    int prepBlocks  = BS / 16;                  // 256 (one A tile per block)
    int wconvBlocks = (V / 16 + 7) / 8;         // 250 (8 W pairs per block)
    prep_all_kernel<<<prepBlocks + wconvBlocks, 256>>>(
        ids, mask, We, gates, Wout, BS, depth, S, B, V, prepBlocks);

    dim3 grid(V / 128, BS / 128);     // (250, 32)
    hmma_gemm_kernel<<<grid, 256>>>(bout, out, V);
}